// round 2
// baseline (speedup 1.0000x reference)
#include <cuda_runtime.h>
#include <cuda_bf16.h>

#define NBLK 2048
#define NTHR 256

// Per-block partial sums (scratch; no dynamic allocation allowed).
__device__ float g_partials[NBLK];

// Main kernel: 4 lanes cooperate on one row of 16 floats.
// Lane c of a group loads float4 #c of the row -> warp-contiguous 512B loads.
__global__ void __launch_bounds__(NTHR)
ce_main(const float4* __restrict__ pred,
        const float4* __restrict__ targ,
        const float*  __restrict__ P,
        int n_vec4 /* = B*4 */) {
    __shared__ float sP[256];
    const int tid = threadIdx.x;
    if (tid < 256) sP[tid] = P[tid];
    __syncthreads();

    const int lane4 = tid & 3;
    const int stride = NBLK * NTHR;
    float acc = 0.f;

    for (int idx = blockIdx.x * NTHR + tid; idx < n_vec4; idx += stride) {
        // ---- loads (both rows share the same float4 index) ----
        float4 pv = pred[idx];
        float4 tv = targ[idx];

        // ---- argmax(predict) over this lane's 4 elements ----
        float bv = pv.x; int bi = lane4 * 4;
        if (pv.y > bv) { bv = pv.y; bi = lane4 * 4 + 1; }
        if (pv.z > bv) { bv = pv.z; bi = lane4 * 4 + 2; }
        if (pv.w > bv) { bv = pv.w; bi = lane4 * 4 + 3; }
        // butterfly across the 4-lane group (first-occurrence tie-break)
        #pragma unroll
        for (int m = 1; m <= 2; m <<= 1) {
            float ov = __shfl_xor_sync(0xffffffffu, bv, m);
            int   oi = __shfl_xor_sync(0xffffffffu, bi, m);
            if (ov > bv || (ov == bv && oi < bi)) { bv = ov; bi = oi; }
        }

        // ---- softmax denominator: sum exp(x - max); p_at_pre = 1/sum ----
        float s = __expf(pv.x - bv) + __expf(pv.y - bv)
                + __expf(pv.z - bv) + __expf(pv.w - bv);
        s += __shfl_xor_sync(0xffffffffu, s, 1);
        s += __shfl_xor_sync(0xffffffffu, s, 2);

        // ---- argmax(target) ----
        float cv = tv.x; int ci = lane4 * 4;
        if (tv.y > cv) { cv = tv.y; ci = lane4 * 4 + 1; }
        if (tv.z > cv) { cv = tv.z; ci = lane4 * 4 + 2; }
        if (tv.w > cv) { cv = tv.w; ci = lane4 * 4 + 3; }
        #pragma unroll
        for (int m = 1; m <= 2; m <<= 1) {
            float ov = __shfl_xor_sync(0xffffffffu, cv, m);
            int   oi = __shfl_xor_sync(0xffffffffu, ci, m);
            if (ov > cv || (ov == cv && oi < ci)) { cv = ov; ci = oi; }
        }

        // ---- weighted contribution (one lane per group) ----
        if (lane4 == 0) {
            float w = (bi == ci) ? 0.f : sP[ci * 16 + bi];
            acc += __fdividef(w, s);
        }
    }

    // ---- block reduction (deterministic order) ----
    #pragma unroll
    for (int m = 16; m >= 1; m >>= 1)
        acc += __shfl_xor_sync(0xffffffffu, acc, m);

    __shared__ float swarp[NTHR / 32];
    if ((tid & 31) == 0) swarp[tid >> 5] = acc;
    __syncthreads();
    if (tid == 0) {
        float v = 0.f;
        #pragma unroll
        for (int w = 0; w < NTHR / 32; w++) v += swarp[w];
        g_partials[blockIdx.x] = v;
    }
}

// Final reduction: one block, deterministic tree, writes mean.
__global__ void __launch_bounds__(NTHR)
ce_reduce(float* __restrict__ out, float invB) {
    __shared__ float s[NTHR];
    float v = 0.f;
    for (int i = threadIdx.x; i < NBLK; i += NTHR) v += g_partials[i];
    s[threadIdx.x] = v;
    __syncthreads();
    #pragma unroll
    for (int k = NTHR / 2; k > 0; k >>= 1) {
        if (threadIdx.x < k) s[threadIdx.x] += s[threadIdx.x + k];
        __syncthreads();
    }
    if (threadIdx.x == 0) out[0] = s[0] * invB;
}

extern "C" void kernel_launch(void* const* d_in, const int* in_sizes, int n_in,
                              void* d_out, int out_size) {
    const float* predict = (const float*)d_in[0];
    const float* target  = (const float*)d_in[1];
    const float* penalty = (const float*)d_in[2];
    float* out = (float*)d_out;

    const int B = in_sizes[0] / 16;      // rows
    const int n_vec4 = B * 4;            // float4 count per tensor

    ce_main<<<NBLK, NTHR>>>((const float4*)predict, (const float4*)target,
                            penalty, n_vec4);
    ce_reduce<<<1, NTHR>>>(out, 1.0f / (float)B);
}

// round 3
// speedup vs baseline: 1.0860x; 1.0860x over previous
#include <cuda_runtime.h>
#include <cuda_bf16.h>

#define NTHR 256
#define VPT  4          // float4 chunks per thread per tensor
#define MAXBLK 8192     // supports up to MAXBLK*NTHR*VPT float4s = 8.39M (B = 2M rows)

__device__ float        g_partials[MAXBLK];
__device__ unsigned int g_count = 0;

// Fused: per-row weighted softmax-at-argmax + full mean reduction.
// 4 lanes cooperate per row of 16 floats (lane c holds float4 #c).
__global__ void __launch_bounds__(NTHR)
ce_fused(const float4* __restrict__ pred,
         const float4* __restrict__ targ,
         const float*  __restrict__ P,
         int n_vec4, float invB, float* __restrict__ out) {
    __shared__ float sP[256];
    const int tid = threadIdx.x;
    if (tid < 256) sP[tid] = P[tid];
    __syncthreads();

    const int lane4 = tid & 3;
    const int base  = blockIdx.x * (NTHR * VPT) + tid;

    // ---- issue all loads up front (MLP = 8 x 16B per thread) ----
    float4 pv[VPT], tv[VPT];
    bool   ok[VPT];
    #pragma unroll
    for (int k = 0; k < VPT; k++) {
        int idx = base + k * NTHR;
        ok[k] = (idx < n_vec4);
        int cidx = ok[k] ? idx : (n_vec4 - 1);   // clamp: keep warp convergent
        pv[k] = __ldcs(pred + cidx);
        tv[k] = __ldcs(targ + cidx);
    }

    float acc = 0.f;
    #pragma unroll
    for (int k = 0; k < VPT; k++) {
        // argmax(predict) within lane's 4 elems
        float bv = pv[k].x; int bi = lane4 * 4;
        if (pv[k].y > bv) { bv = pv[k].y; bi = lane4 * 4 + 1; }
        if (pv[k].z > bv) { bv = pv[k].z; bi = lane4 * 4 + 2; }
        if (pv[k].w > bv) { bv = pv[k].w; bi = lane4 * 4 + 3; }
        #pragma unroll
        for (int m = 1; m <= 2; m <<= 1) {
            float ov = __shfl_xor_sync(0xffffffffu, bv, m);
            int   oi = __shfl_xor_sync(0xffffffffu, bi, m);
            if (ov > bv || (ov == bv && oi < bi)) { bv = ov; bi = oi; }
        }

        // softmax denom: sum exp(x - max); p_at_pre = 1/s
        float s = __expf(pv[k].x - bv) + __expf(pv[k].y - bv)
                + __expf(pv[k].z - bv) + __expf(pv[k].w - bv);
        s += __shfl_xor_sync(0xffffffffu, s, 1);
        s += __shfl_xor_sync(0xffffffffu, s, 2);

        // argmax(target)
        float cv = tv[k].x; int ci = lane4 * 4;
        if (tv[k].y > cv) { cv = tv[k].y; ci = lane4 * 4 + 1; }
        if (tv[k].z > cv) { cv = tv[k].z; ci = lane4 * 4 + 2; }
        if (tv[k].w > cv) { cv = tv[k].w; ci = lane4 * 4 + 3; }
        #pragma unroll
        for (int m = 1; m <= 2; m <<= 1) {
            float ov = __shfl_xor_sync(0xffffffffu, cv, m);
            int   oi = __shfl_xor_sync(0xffffffffu, ci, m);
            if (ov > cv || (ov == cv && oi < ci)) { cv = ov; ci = oi; }
        }

        if (lane4 == 0 && ok[k]) {
            float w = (bi == ci) ? 0.f : sP[ci * 16 + bi];
            acc += __fdividef(w, s);
        }
    }

    // ---- deterministic block reduction ----
    #pragma unroll
    for (int m = 16; m >= 1; m >>= 1)
        acc += __shfl_xor_sync(0xffffffffu, acc, m);

    __shared__ float swarp[NTHR / 32];
    if ((tid & 31) == 0) swarp[tid >> 5] = acc;
    __syncthreads();
    if (tid == 0) {
        float v = 0.f;
        #pragma unroll
        for (int w = 0; w < NTHR / 32; w++) v += swarp[w];
        g_partials[blockIdx.x] = v;
    }

    // ---- last-block-done final reduction (deterministic order) ----
    __shared__ bool amLast;
    if (tid == 0) {
        __threadfence();
        unsigned prev = atomicAdd(&g_count, 1u);
        amLast = (prev == gridDim.x - 1);
    }
    __syncthreads();
    if (amLast) {
        const int nblk = gridDim.x;
        float v = 0.f;
        for (int i = tid; i < nblk; i += NTHR) v += g_partials[i];  // fixed order
        __shared__ float s[NTHR];
        s[tid] = v;
        __syncthreads();
        #pragma unroll
        for (int kk = NTHR / 2; kk > 0; kk >>= 1) {
            if (tid < kk) s[tid] += s[tid + kk];
            __syncthreads();
        }
        if (tid == 0) {
            out[0]   = s[0] * invB;
            g_count  = 0;            // reset for next graph replay
        }
    }
}

extern "C" void kernel_launch(void* const* d_in, const int* in_sizes, int n_in,
                              void* d_out, int out_size) {
    const float* predict = (const float*)d_in[0];
    const float* target  = (const float*)d_in[1];
    const float* penalty = (const float*)d_in[2];
    float* out = (float*)d_out;

    const int B      = in_sizes[0] / 16;
    const int n_vec4 = B * 4;
    int nblk = (n_vec4 + NTHR * VPT - 1) / (NTHR * VPT);
    if (nblk > MAXBLK) nblk = MAXBLK;   // dataset shape: exactly 8192

    ce_fused<<<nblk, NTHR>>>((const float4*)predict, (const float4*)target,
                             penalty, n_vec4, 1.0f / (float)B, out);
}